// round 3
// baseline (speedup 1.0000x reference)
#include <cuda_runtime.h>
#include <math.h>

#define BB 2
#define CC 128
#define HH 48
#define WW 48
#define PP (HH*WW)      // 2304
#define HD 24
#define WIN 13
#define KK2 169
#define NG 32

// ---------------- scratch (static device globals; no allocation) ----------------
__device__ float g_down[BB*CC*HD*HD];
__device__ float g_xn[BB*PP*CC];     // normalized x, pixel-major [b,p,c]
__device__ float g_m[BB*PP];         // max(||x_p||, 1e-12)
__device__ float g_df[BB*PP];
__device__ int   g_dmin[BB];
__device__ int   g_dmax[BB];
__device__ float g_mu[BB*NG];
__device__ float g_rstd[BB*NG];
__device__ float g_enh[BB*PP*CC];    // enhanced, pixel-major

__device__ __forceinline__ void fma2(unsigned long long& d, unsigned long long a,
                                     unsigned long long b, unsigned long long c) {
    asm("fma.rn.f32x2 %0, %1, %2, %3;" : "=l"(d) : "l"(a), "l"(b), "l"(c));
}
__device__ __forceinline__ float lohi(unsigned long long v) {
    return __int_as_float((int)(v & 0xffffffffull)) + __int_as_float((int)(v >> 32));
}

// ---------------- init ----------------
__global__ void k_init() {
    int t = threadIdx.x;
    if (t < BB) { g_dmin[t] = 0x7f7fffff; g_dmax[t] = 0; }
}

// ---------------- 2x2 average pool (exact jax bilinear 48->24, antialias=False) ----------------
__global__ void k_down(const float* __restrict__ x) {
    int idx = blockIdx.x * 256 + threadIdx.x;      // 147456 exact
    int ow = idx % HD; int tmp = idx / HD;
    int oh = tmp % HD; tmp /= HD;                  // tmp = b*CC + c
    const float* xp = x + (tmp * HH + 2 * oh) * WW + 2 * ow;
    g_down[idx] = 0.25f * (xp[0] + xp[1] + xp[WW] + xp[WW + 1]);
}

// upsample 24->48 weights (jax bilinear, edge-renormalized triangle kernel)
__device__ __forceinline__ void upw(int o, int& i0, float& w0, int& i1, float& w1v) {
    if (o & 1) { i0 = (o - 1) >> 1; i1 = i0 + 1; w0 = 0.75f; w1v = 0.25f;
                 if (i1 >= HD) { i1 = i0; w0 = 1.0f; w1v = 0.0f; } }
    else       { i1 = o >> 1; i0 = i1 - 1; w1v = 0.75f; w0 = 0.25f;
                 if (i0 < 0) { i0 = i1; w0 = 0.0f; w1v = 1.0f; } }
}

// ---------------- per-pixel: df, norm, normalized vector ----------------
__global__ void __launch_bounds__(128) k_pix(const float* __restrict__ x) {
    int pix = blockIdx.x;                 // b*PP + p
    int b = pix / PP, p = pix % PP;
    int h = p / WW, w = p % WW;
    int c = threadIdx.x;
    float v = x[((b * CC + c) * HH + h) * WW + w];

    int r0, r1, c0, c1; float wr0, wr1, wc0, wc1;
    upw(h, r0, wr0, r1, wr1);
    upw(w, c0, wc0, c1, wc1);
    const float* d = g_down + (b * CC + c) * HD * HD;
    float xdu = wr0 * (wc0 * d[r0 * HD + c0] + wc1 * d[r0 * HD + c1])
              + wr1 * (wc0 * d[r1 * HD + c0] + wc1 * d[r1 * HD + c1]);

    float a = fabsf(v - xdu);
    float q = v * v;
    #pragma unroll
    for (int off = 16; off; off >>= 1) {
        a += __shfl_xor_sync(~0u, a, off);
        q += __shfl_xor_sync(~0u, q, off);
    }
    __shared__ float sA[4], sQ[4];
    __shared__ float sM;
    int wi = c >> 5, lane = c & 31;
    if (lane == 0) { sA[wi] = a; sQ[wi] = q; }
    __syncthreads();
    if (c == 0) {
        float df = sA[0] + sA[1] + sA[2] + sA[3];
        float sq = sQ[0] + sQ[1] + sQ[2] + sQ[3];
        g_df[pix] = df;
        atomicMin(&g_dmin[b], __float_as_int(df));   // df >= 0: int order == float order
        atomicMax(&g_dmax[b], __float_as_int(df));
        float m = fmaxf(sqrtf(sq), 1e-12f);
        g_m[pix] = m;
        sM = m;
    }
    __syncthreads();
    g_xn[pix * CC + c] = v / sM;
}

// ---------------- GroupNorm stats (per (b,g): 4 ch x 2304 px contiguous) ----------------
__global__ void __launch_bounds__(256) k_gn(const float* __restrict__ x) {
    int bg = blockIdx.x; int b = bg >> 5, g = bg & 31;
    const float* base = x + (b * CC + g * 4) * PP;
    float s = 0.f, q = 0.f;
    for (int i = threadIdx.x; i < 4 * PP; i += 256) {
        float v = base[i]; s += v; q += v * v;
    }
    #pragma unroll
    for (int off = 16; off; off >>= 1) {
        s += __shfl_xor_sync(~0u, s, off);
        q += __shfl_xor_sync(~0u, q, off);
    }
    __shared__ float sS[8], sQ2[8];
    int wi = threadIdx.x >> 5;
    if ((threadIdx.x & 31) == 0) { sS[wi] = s; sQ2[wi] = q; }
    __syncthreads();
    if (threadIdx.x == 0) {
        float ts = 0.f, tq = 0.f;
        #pragma unroll
        for (int i = 0; i < 8; i++) { ts += sS[i]; tq += sQ2[i]; }
        const float invn = 1.0f / (float)(4 * PP);
        float mu = ts * invn;
        float var = tq * invn - mu * mu;
        g_mu[bg] = mu;
        g_rstd[bg] = rsqrtf(var + 1e-5f);
    }
}

__device__ __forceinline__ int refl(int v, int n) {
    return v < 0 ? -v : (v >= n ? 2 * n - 2 - v : v);
}

// ---------------- main: sims + stable top-k + weighted gather + GN fuse ----------------
__global__ void __launch_bounds__(256) k_main(const float* __restrict__ gamma,
                                              const float* __restrict__ beta) {
    __shared__ float ssim[8][176];
    int warp = threadIdx.x >> 5, lane = threadIdx.x & 31;
    int pix = blockIdx.x * 8 + warp;             // 576*8 = 4608 exact
    int b = pix / PP, p = pix % PP;
    int h = p / WW, w = p % WW;
    const float* xnb = g_xn + b * PP * CC;
    float4 xp4 = *(const float4*)(xnb + p * CC + 4 * lane);

    // connection count k
    float df = g_df[pix];
    float dmin = __int_as_float(g_dmin[b]);
    float dmax = __int_as_float(g_dmax[b]);
    float dn = (df - dmin) / (dmax - dmin + 1e-8f);
    int kcnt = (int)(1.0f + rintf(dn * 15.0f));  // rintf: round-half-even == jnp.round
    if (kcnt < 1) kcnt = 1;
    if (kcnt > 16) kcnt = 16;

    int qoff[WIN];
    #pragma unroll
    for (int t = 0; t < WIN; t++) qoff[t] = refl(w + t - 6, WW);

    // ---- 169 cosine sims: sim = <xn_p, xn_q>, warp butterfly reduce ----
    int kidx = 0;
    for (int i = 0; i < WIN; i++) {
        int r = refl(h + i - 6, HH);
        const float* rowp = xnb + r * WW * CC + 4 * lane;
        #pragma unroll
        for (int j = 0; j < WIN; j++) {
            const float4 vq = *(const float4*)(rowp + qoff[j] * CC);
            float dt = xp4.x * vq.x + xp4.y * vq.y + xp4.z * vq.z + xp4.w * vq.w;
            #pragma unroll
            for (int off = 16; off; off >>= 1) dt += __shfl_xor_sync(~0u, dt, off);
            if (lane == 0) ssim[warp][kidx + j] = dt;
        }
        kidx += WIN;
    }
    __syncwarp();

    // lane l owns sims at k = l, l+32, ..., l+160 (static register slots)
    float sreg[6];
    #pragma unroll
    for (int t = 0; t < 6; t++) {
        int kk = lane + 32 * t;
        sreg[t] = (kk < KK2) ? ssim[warp][kk] : -1e30f;
    }

    // ---- iterative top-k: max value, tie -> smallest index (== stable argsort mask) ----
    unsigned taken = 0;
    int selk[16]; float selw[16];
    float sumexp = 0.f;
    #pragma unroll
    for (int it = 0; it < 16; it++) {
        if (it < kcnt) {                          // kcnt is warp-uniform
            float bv = -1e30f; int bt = 0;
            #pragma unroll
            for (int t = 0; t < 6; t++) {
                float cand = (taken & (1u << t)) ? -1e30f : sreg[t];
                if (cand > bv) { bv = cand; bt = t; }   // strict > keeps smallest index
            }
            int bk = lane + 32 * bt;
            #pragma unroll
            for (int off = 16; off; off >>= 1) {
                float ov = __shfl_xor_sync(~0u, bv, off);
                int   ok = __shfl_xor_sync(~0u, bk, off);
                if (ov > bv || (ov == bv && ok < bk)) { bv = ov; bk = ok; }
            }
            if (lane == (bk & 31)) taken |= (1u << (bk >> 5));
            float e = expf(bv);
            selk[it] = bk; selw[it] = e; sumexp += e;
        }
    }

    // ---- weighted aggregation: out = sum w_k * (xn_q * m_q) ----
    float inv = 1.0f / sumexp;
    float4 out4 = make_float4(0.f, 0.f, 0.f, 0.f);
    #pragma unroll
    for (int it = 0; it < 16; it++) {
        if (it < kcnt) {
            int kk = selk[it];
            int ii = kk / WIN, jj = kk - ii * WIN;
            int r = refl(h + ii - 6, HH);
            int cq = refl(w + jj - 6, WW);
            int q = r * WW + cq;
            float wgt = selw[it] * inv * g_m[b * PP + q];
            const float4 vq = *(const float4*)(xnb + q * CC + 4 * lane);
            out4.x += wgt * vq.x; out4.y += wgt * vq.y;
            out4.z += wgt * vq.z; out4.w += wgt * vq.w;
        }
    }

    // ---- GroupNorm fuse: group g == lane (c = 4*lane .. 4*lane+3) ----
    float mp = g_m[pix];
    float mu = g_mu[b * NG + lane];
    float rs = g_rstd[b * NG + lane];
    float4 gm  = *(const float4*)(gamma + 4 * lane);
    float4 bt4 = *(const float4*)(beta + 4 * lane);
    float4 e4;
    e4.x = out4.x + (xp4.x * mp - mu) * rs * gm.x + bt4.x;
    e4.y = out4.y + (xp4.y * mp - mu) * rs * gm.y + bt4.y;
    e4.z = out4.z + (xp4.z * mp - mu) * rs * gm.z + bt4.z;
    e4.w = out4.w + (xp4.w * mp - mu) * rs * gm.w + bt4.w;
    *(float4*)(g_enh + pix * CC + 4 * lane) = e4;
}

// ---------------- FFN: final = e + W2 @ relu(W1 @ e + b1) + b2, NCHW write ----------------
// One block per 32 pixels; 256 threads. f32x2 packed FMA throughout.
__global__ void __launch_bounds__(256) k_ffn(const float* __restrict__ w1,
                                             const float* __restrict__ b1,
                                             const float* __restrict__ w2,
                                             const float* __restrict__ b2,
                                             float* __restrict__ out) {
    __shared__ __align__(16) float sE[32 * 128];   // 16 KB
    __shared__ __align__(16) float sH[32 * 256];   // 32 KB (total 48 KB)
    int tid = threadIdx.x;
    int pix0 = blockIdx.x * 32;
    int b = pix0 / PP;

    // load E tile (coalesced float4)
    const float4* eg = (const float4*)g_enh + pix0 * 32;
    float4* es4 = (float4*)sE;
    #pragma unroll
    for (int i = 0; i < 4; i++) es4[tid + 256 * i] = eg[tid + 256 * i];
    __syncthreads();

    // GEMM1: thread t = hidden unit o; 32 pixels in registers
    {
        unsigned long long acc[32];
        #pragma unroll
        for (int p = 0; p < 32; p++) acc[p] = 0ull;
        const unsigned long long* w1v = (const unsigned long long*)w1 + tid * 64;
        const unsigned long long* ev = (const unsigned long long*)sE;
        #pragma unroll 4
        for (int c2 = 0; c2 < 64; c2++) {
            unsigned long long wv = w1v[c2];
            #pragma unroll
            for (int p = 0; p < 32; p++)
                fma2(acc[p], wv, ev[p * 64 + c2], acc[p]);
        }
        float bias = b1[tid];
        #pragma unroll
        for (int p = 0; p < 32; p++)
            sH[p * 256 + tid] = fmaxf(lohi(acc[p]) + bias, 0.0f);
    }
    __syncthreads();

    // GEMM2: thread t -> (c = t&127, half = t>>7); 16 pixels each
    {
        int c = tid & 127, half = tid >> 7, p0 = half * 16;
        unsigned long long acc[16];
        #pragma unroll
        for (int p = 0; p < 16; p++) acc[p] = 0ull;
        const unsigned long long* w2v = (const unsigned long long*)w2 + c * 128;
        const unsigned long long* hv = (const unsigned long long*)sH + p0 * 128;
        #pragma unroll 4
        for (int o2 = 0; o2 < 128; o2++) {
            unsigned long long wv = w2v[o2];
            #pragma unroll
            for (int p = 0; p < 16; p++)
                fma2(acc[p], wv, hv[p * 128 + o2], acc[p]);
        }
        float bias = b2[c];
        float* og = out + (b * CC + c) * PP + (pix0 - b * PP) + p0;
        #pragma unroll
        for (int p4 = 0; p4 < 4; p4++) {
            float4 r;
            r.x = sE[(p0 + 4 * p4 + 0) * 128 + c] + lohi(acc[4 * p4 + 0]) + bias;
            r.y = sE[(p0 + 4 * p4 + 1) * 128 + c] + lohi(acc[4 * p4 + 1]) + bias;
            r.z = sE[(p0 + 4 * p4 + 2) * 128 + c] + lohi(acc[4 * p4 + 2]) + bias;
            r.w = sE[(p0 + 4 * p4 + 3) * 128 + c] + lohi(acc[4 * p4 + 3]) + bias;
            *(float4*)(og + 4 * p4) = r;
        }
    }
}

extern "C" void kernel_launch(void* const* d_in, const int* in_sizes, int n_in,
                              void* d_out, int out_size) {
    const float* x     = (const float*)d_in[0];
    const float* gamma = (const float*)d_in[1];
    const float* beta  = (const float*)d_in[2];
    const float* w1    = (const float*)d_in[3];
    const float* b1    = (const float*)d_in[4];
    const float* w2    = (const float*)d_in[5];
    const float* b2    = (const float*)d_in[6];
    float* out = (float*)d_out;

    k_init<<<1, 32>>>();
    k_down<<<(BB * CC * HD * HD) / 256, 256>>>(x);
    k_pix<<<BB * PP, 128>>>(x);
    k_gn<<<BB * NG, 256>>>(x);
    k_main<<<(BB * PP) / 8, 256>>>(gamma, beta);
    k_ffn<<<(BB * PP) / 32, 256>>>(w1, b1, w2, b2, out);
}

// round 6
// speedup vs baseline: 1.1842x; 1.1842x over previous
#include <cuda_runtime.h>
#include <math.h>

#define BB 2
#define CC 128
#define HH 48
#define WW 48
#define PP (HH*WW)      // 2304
#define HD 24
#define DD (HD*HD)      // 576
#define WIN 13
#define KK2 169
#define NG 32
#define NT 72           // pixel tiles (2304/32)

// ---------------- scratch (static device globals; no allocation) ----------------
__device__ float g_xt[BB*PP*CC];     // x transposed, pixel-major [b,p,c]
__device__ float g_dt[BB*DD*CC];     // downsampled, pixel-major [b,od,c]
__device__ float g_xn[BB*PP*CC];     // normalized x, pixel-major
__device__ float g_m[BB*PP];
__device__ float g_df[BB*PP];
__device__ int   g_dmin[BB];
__device__ int   g_dmax[BB];
__device__ float g_gps[BB*NG*NT];    // GN partial sums (deterministic slots)
__device__ float g_gpq[BB*NG*NT];
__device__ float g_mu[BB*NG];
__device__ float g_rstd[BB*NG];
__device__ float g_enh[BB*PP*CC];

__device__ __forceinline__ void fma2(unsigned long long& d, unsigned long long a,
                                     unsigned long long b, unsigned long long c) {
    asm("fma.rn.f32x2 %0, %1, %2, %3;" : "=l"(d) : "l"(a), "l"(b), "l"(c));
}
__device__ __forceinline__ float lohi(unsigned long long v) {
    return __int_as_float((int)(v & 0xffffffffull)) + __int_as_float((int)(v >> 32));
}
__device__ __forceinline__ int refl(int v, int n) {
    return v < 0 ? -v : (v >= n ? 2 * n - 2 - v : v);
}
// jax bilinear 24->48 weights (edge-renormalized triangle)
__device__ __forceinline__ void upw(int o, int& i0, float& w0, int& i1, float& w1v) {
    if (o & 1) { i0 = (o - 1) >> 1; i1 = i0 + 1; w0 = 0.75f; w1v = 0.25f;
                 if (i1 >= HD) { i1 = i0; w0 = 1.0f; w1v = 0.0f; } }
    else       { i1 = o >> 1; i0 = i1 - 1; w1v = 0.75f; w0 = 0.25f;
                 if (i0 < 0) { i0 = i1; w0 = 0.0f; w1v = 1.0f; } }
}

// ---------------- k_t: NCHW -> pixel-major transpose + GN partial sums + init ----------------
__global__ void __launch_bounds__(256) k_t(const float* __restrict__ x) {
    __shared__ float tile[32][33];
    __shared__ float sS[8][4], sQ[8][4];
    int tx = threadIdx.x & 31, ty = threadIdx.x >> 5;
    int tb = blockIdx.x, cb = blockIdx.y, b = blockIdx.z;
    if (tb == 0 && cb == 0 && b == 0 && threadIdx.x < BB) {
        g_dmin[threadIdx.x] = 0x7f7fffff; g_dmax[threadIdx.x] = 0;
    }
    int c0 = cb * 32, p0 = tb * 32;
    #pragma unroll
    for (int k = 0; k < 4; k++) {
        int c = c0 + ty + 8 * k;
        float v = x[(b * CC + c) * PP + p0 + tx];        // coalesced over tx
        tile[ty + 8 * k][tx] = v;
        float s = v, q = v * v;
        #pragma unroll
        for (int off = 16; off; off >>= 1) {
            s += __shfl_xor_sync(~0u, s, off);
            q += __shfl_xor_sync(~0u, q, off);
        }
        if (tx == 0) { sS[ty][k] = s; sQ[ty][k] = q; }
    }
    __syncthreads();
    #pragma unroll
    for (int k = 0; k < 4; k++) {
        int p = p0 + ty + 8 * k;
        g_xt[(b * PP + p) * CC + c0 + tx] = tile[tx][ty + 8 * k];  // coalesced over tx
    }
    // per-block group partials: group_local gl = 2k+m; channels c0+8k+4m..+3
    if (threadIdx.x < 8) {
        int k = threadIdx.x >> 1, m = threadIdx.x & 1;
        float s = sS[4*m][k] + sS[4*m+1][k] + sS[4*m+2][k] + sS[4*m+3][k];
        float q = sQ[4*m][k] + sQ[4*m+1][k] + sQ[4*m+2][k] + sQ[4*m+3][k];
        int g = 8 * cb + threadIdx.x;
        g_gps[(b * NG + g) * NT + tb] = s;
        g_gpq[(b * NG + g) * NT + tb] = q;
    }
}

// ---------------- k_down: 2x2 mean in pixel-major + GN finalize ----------------
__global__ void __launch_bounds__(256) k_down() {
    int idx = blockIdx.x * 256 + threadIdx.x;     // 2*576*128 = 147456 exact
    int c = idx & 127;
    int rest = idx >> 7;                          // b*DD + od
    int b = rest / DD, od = rest - b * DD;
    int oh = od / HD, ow = od - oh * HD;
    int p00 = (2 * oh) * WW + 2 * ow;
    const float* xb = g_xt + b * PP * CC;
    g_dt[idx] = 0.25f * (xb[p00 * CC + c] + xb[(p00 + 1) * CC + c] +
                         xb[(p00 + WW) * CC + c] + xb[(p00 + WW + 1) * CC + c]);
    if (blockIdx.x < BB * NG) {                   // block-uniform branch
        __shared__ float fs[NT], fq[NT];
        int bg = blockIdx.x;
        if (threadIdx.x < NT) {
            fs[threadIdx.x] = g_gps[bg * NT + threadIdx.x];
            fq[threadIdx.x] = g_gpq[bg * NT + threadIdx.x];
        }
        __syncthreads();
        if (threadIdx.x == 0) {
            float s = 0.f, q = 0.f;
            for (int i = 0; i < NT; i++) { s += fs[i]; q += fq[i]; }
            const float invn = 1.0f / (4.0f * PP);
            float mu = s * invn;
            float var = q * invn - mu * mu;
            g_mu[bg] = mu;
            g_rstd[bg] = rsqrtf(var + 1e-5f);
        }
    }
}

// ---------------- k_pix: df, norm, normalized vector (all coalesced) ----------------
__global__ void __launch_bounds__(128) k_pix() {
    int pix = blockIdx.x;
    int b = pix / PP, p = pix - b * PP;
    int h = p / WW, w = p - h * WW;
    int c = threadIdx.x;
    float v = g_xt[pix * CC + c];

    int r0, r1, c0, c1; float wr0, wr1, wc0, wc1;
    upw(h, r0, wr0, r1, wr1);
    upw(w, c0, wc0, c1, wc1);
    const float* db = g_dt + b * DD * CC;
    float xdu = wr0 * (wc0 * db[(r0 * HD + c0) * CC + c] + wc1 * db[(r0 * HD + c1) * CC + c])
              + wr1 * (wc0 * db[(r1 * HD + c0) * CC + c] + wc1 * db[(r1 * HD + c1) * CC + c]);

    float a = fabsf(v - xdu);
    float q = v * v;
    #pragma unroll
    for (int off = 16; off; off >>= 1) {
        a += __shfl_xor_sync(~0u, a, off);
        q += __shfl_xor_sync(~0u, q, off);
    }
    __shared__ float sA[4], sQ[4];
    __shared__ float sM;
    int wi = c >> 5, lane = c & 31;
    if (lane == 0) { sA[wi] = a; sQ[wi] = q; }
    __syncthreads();
    if (c == 0) {
        float df = sA[0] + sA[1] + sA[2] + sA[3];
        float sq = sQ[0] + sQ[1] + sQ[2] + sQ[3];
        g_df[pix] = df;
        atomicMin(&g_dmin[b], __float_as_int(df));   // df >= 0: int order == float order
        atomicMax(&g_dmax[b], __float_as_int(df));
        float m = fmaxf(sqrtf(sq), 1e-12f);
        g_m[pix] = m;
        sM = m;
    }
    __syncthreads();
    g_xn[pix * CC + c] = v / sM;
}

// ---------------- k_main: sims (multi-value warp reduce) + stable top-k + gather + GN ----------------
__global__ void __launch_bounds__(256) k_main(const float* __restrict__ gamma,
                                              const float* __restrict__ beta) {
    int warp = threadIdx.x >> 5, lane = threadIdx.x & 31;
    int pix = blockIdx.x * 8 + warp;             // 576*8 = 4608 exact
    int b = pix / PP, p = pix - b * PP;
    int h = p / WW, w = p - h * WW;
    const float* xnb = g_xn + b * PP * CC;
    const float4 xp4 = *(const float4*)(xnb + p * CC + 4 * lane);

    float df = g_df[pix];
    float dmin = __int_as_float(g_dmin[b]);
    float dmax = __int_as_float(g_dmax[b]);
    float dn = (df - dmin) / (dmax - dmin + 1e-8f);
    int kcnt = (int)(1.0f + rintf(dn * 15.0f));  // round-half-even == jnp.round
    if (kcnt < 1) kcnt = 1;
    if (kcnt > 16) kcnt = 16;

    int rbase[WIN], qo[WIN];                      // compile-time indexed only -> registers
    #pragma unroll
    for (int t = 0; t < WIN; t++) {
        rbase[t] = refl(h + t - 6, HH) * WW * CC;
        qo[t]    = refl(w + t - 6, WW) * CC;
    }

    // ---- sims: 6 rounds of 32 neighbors; 31-shuffle transposed butterfly per round ----
    float sreg[6];
    #pragma unroll
    for (int r = 0; r < 6; r++) {
        float v[32];
        #pragma unroll
        for (int jj = 0; jj < 32; jj++) {
            const int kk = r * 32 + jj;                       // compile-time
            const int ii = (kk < KK2) ? kk / WIN : 0;
            const int ij = (kk < KK2) ? kk - ii * WIN : 0;
            const float4 vq = *(const float4*)(xnb + rbase[ii] + qo[ij] + 4 * lane);
            v[jj] = xp4.x * vq.x + xp4.y * vq.y + xp4.z * vq.z + xp4.w * vq.w;
        }
        #pragma unroll
        for (int off = 16; off >= 1; off >>= 1) {
            bool up = (lane & off) != 0;
            #pragma unroll
            for (int j = 0; j < off; j++) {
                float send = up ? v[j] : v[j + off];
                float recv = __shfl_xor_sync(~0u, send, off);
                v[j] = (up ? v[j + off] : v[j]) + recv;
            }
        }
        sreg[r] = v[0];                           // lane l holds sim for neighbor r*32+l
    }
    if (160 + lane >= KK2) sreg[5] = -1e30f;      // mask padded slots

    // ---- iterative top-k: max value, tie -> smallest index (stable argsort mask) ----
    unsigned taken = 0;
    int selk[16]; float selw[16];
    float sumexp = 0.f;
    #pragma unroll
    for (int it = 0; it < 16; it++) {
        if (it < kcnt) {                          // kcnt warp-uniform
            float bv = -1e30f; int bt = 0;
            #pragma unroll
            for (int t = 0; t < 6; t++) {
                float cand = (taken & (1u << t)) ? -1e30f : sreg[t];
                if (cand > bv) { bv = cand; bt = t; }
            }
            int bk = lane + 32 * bt;
            #pragma unroll
            for (int off = 16; off; off >>= 1) {
                float ov = __shfl_xor_sync(~0u, bv, off);
                int   ok = __shfl_xor_sync(~0u, bk, off);
                if (ov > bv || (ov == bv && ok < bk)) { bv = ov; bk = ok; }
            }
            if (lane == (bk & 31)) taken |= (1u << (bk >> 5));
            float e = expf(bv);
            selk[it] = bk; selw[it] = e; sumexp += e;
        }
    }

    // ---- weighted aggregation: out = sum w_k * (xn_q * m_q) ----
    float inv = 1.0f / sumexp;
    float4 out4 = make_float4(0.f, 0.f, 0.f, 0.f);
    #pragma unroll
    for (int it = 0; it < 16; it++) {
        if (it < kcnt) {
            int kk = selk[it];
            int ii = kk / WIN, jj = kk - ii * WIN;
            int r = refl(h + ii - 6, HH);
            int cq = refl(w + jj - 6, WW);
            int q = r * WW + cq;
            float wgt = selw[it] * inv * g_m[b * PP + q];
            const float4 vq = *(const float4*)(xnb + q * CC + 4 * lane);
            out4.x += wgt * vq.x; out4.y += wgt * vq.y;
            out4.z += wgt * vq.z; out4.w += wgt * vq.w;
        }
    }

    // ---- GroupNorm fuse: group == lane (c = 4*lane..4*lane+3) ----
    float mp = g_m[pix];
    float mu = g_mu[b * NG + lane];
    float rs = g_rstd[b * NG + lane];
    float4 gm  = *(const float4*)(gamma + 4 * lane);
    float4 bt4 = *(const float4*)(beta + 4 * lane);
    float4 e4;
    e4.x = out4.x + (xp4.x * mp - mu) * rs * gm.x + bt4.x;
    e4.y = out4.y + (xp4.y * mp - mu) * rs * gm.y + bt4.y;
    e4.z = out4.z + (xp4.z * mp - mu) * rs * gm.z + bt4.z;
    e4.w = out4.w + (xp4.w * mp - mu) * rs * gm.w + bt4.w;
    *(float4*)(g_enh + pix * CC + 4 * lane) = e4;
}

// ---------------- FFN: final = e + W2 @ relu(W1 @ e + b1) + b2, NCHW write ----------------
__global__ void __launch_bounds__(256) k_ffn(const float* __restrict__ w1,
                                             const float* __restrict__ b1,
                                             const float* __restrict__ w2,
                                             const float* __restrict__ b2,
                                             float* __restrict__ out) {
    __shared__ __align__(16) float sE[32 * 128];   // 16 KB
    __shared__ __align__(16) float sH[32 * 256];   // 32 KB
    int tid = threadIdx.x;
    int pix0 = blockIdx.x * 32;
    int b = pix0 / PP;

    const float4* eg = (const float4*)g_enh + pix0 * 32;
    float4* es4 = (float4*)sE;
    #pragma unroll
    for (int i = 0; i < 4; i++) es4[tid + 256 * i] = eg[tid + 256 * i];
    __syncthreads();

    // GEMM1: thread = hidden unit; 32 pixels in registers (f32x2)
    {
        unsigned long long acc[32];
        #pragma unroll
        for (int p = 0; p < 32; p++) acc[p] = 0ull;
        const unsigned long long* w1v = (const unsigned long long*)w1 + tid * 64;
        const unsigned long long* ev = (const unsigned long long*)sE;
        #pragma unroll 4
        for (int c2 = 0; c2 < 64; c2++) {
            unsigned long long wv = w1v[c2];
            #pragma unroll
            for (int p = 0; p < 32; p++)
                fma2(acc[p], wv, ev[p * 64 + c2], acc[p]);
        }
        float bias = b1[tid];
        #pragma unroll
        for (int p = 0; p < 32; p++)
            sH[p * 256 + tid] = fmaxf(lohi(acc[p]) + bias, 0.0f);
    }
    __syncthreads();

    // GEMM2: thread -> (c = t&127, half = t>>7); 16 pixels each
    {
        int c = tid & 127, half = tid >> 7, p0 = half * 16;
        unsigned long long acc[16];
        #pragma unroll
        for (int p = 0; p < 16; p++) acc[p] = 0ull;
        const unsigned long long* w2v = (const unsigned long long*)w2 + c * 128;
        const unsigned long long* hv = (const unsigned long long*)sH + p0 * 128;
        #pragma unroll 4
        for (int o2 = 0; o2 < 128; o2++) {
            unsigned long long wv = w2v[o2];
            #pragma unroll
            for (int p = 0; p < 16; p++)
                fma2(acc[p], wv, hv[p * 128 + o2], acc[p]);
        }
        float bias = b2[c];
        float* og = out + (b * CC + c) * PP + (pix0 - b * PP) + p0;
        #pragma unroll
        for (int p4 = 0; p4 < 4; p4++) {
            float4 r;
            r.x = sE[(p0 + 4 * p4 + 0) * 128 + c] + lohi(acc[4 * p4 + 0]) + bias;
            r.y = sE[(p0 + 4 * p4 + 1) * 128 + c] + lohi(acc[4 * p4 + 1]) + bias;
            r.z = sE[(p0 + 4 * p4 + 2) * 128 + c] + lohi(acc[4 * p4 + 2]) + bias;
            r.w = sE[(p0 + 4 * p4 + 3) * 128 + c] + lohi(acc[4 * p4 + 3]) + bias;
            *(float4*)(og + 4 * p4) = r;
        }
    }
}

extern "C" void kernel_launch(void* const* d_in, const int* in_sizes, int n_in,
                              void* d_out, int out_size) {
    const float* x     = (const float*)d_in[0];
    const float* gamma = (const float*)d_in[1];
    const float* beta  = (const float*)d_in[2];
    const float* w1    = (const float*)d_in[3];
    const float* b1    = (const float*)d_in[4];
    const float* w2    = (const float*)d_in[5];
    const float* b2    = (const float*)d_in[6];
    float* out = (float*)d_out;

    dim3 gT(NT, 4, BB);
    k_t<<<gT, 256>>>(x);
    k_down<<<(BB * DD * CC) / 256, 256>>>();
    k_pix<<<BB * PP, 128>>>();
    k_main<<<(BB * PP) / 8, 256>>>(gamma, beta);
    k_ffn<<<(BB * PP) / 32, 256>>>(w1, b1, w2, b2, out);
}

// round 7
// speedup vs baseline: 1.4961x; 1.2634x over previous
#include <cuda_runtime.h>
#include <math.h>

#define BB 2
#define CC 128
#define HH 48
#define WW 48
#define PP (HH*WW)      // 2304
#define HD 24
#define DD (HD*HD)      // 576
#define WIN 13
#define KK2 169
#define NG 32
#define NT 72           // pixel tiles (2304/32)

typedef unsigned long long ull;

// ---------------- scratch (static device globals; no allocation) ----------------
__device__ float g_xt[BB*PP*CC];     // x transposed, pixel-major [b,p,c]
__device__ float g_dt[BB*DD*CC];     // downsampled, pixel-major [b,od,c]
__device__ float g_xn[BB*PP*CC];     // normalized x, pixel-major
__device__ float g_m[BB*PP];
__device__ float g_df[BB*PP];
__device__ int   g_dmin[BB];
__device__ int   g_dmax[BB];
__device__ float g_gps[BB*NG*NT];    // GN partial sums (deterministic slots)
__device__ float g_gpq[BB*NG*NT];
__device__ float g_mu[BB*NG];
__device__ float g_rstd[BB*NG];
__device__ float g_enh[BB*PP*CC];

__device__ __forceinline__ void fma2(ull& d, ull a, ull b, ull c) {
    asm("fma.rn.f32x2 %0, %1, %2, %3;" : "=l"(d) : "l"(a), "l"(b), "l"(c));
}
__device__ __forceinline__ void add2(ull& d, ull a, ull b) {
    asm("add.rn.f32x2 %0, %1, %2;" : "=l"(d) : "l"(a), "l"(b));
}
__device__ __forceinline__ ull dup2(float v) {
    ull r; unsigned u = __float_as_uint(v);
    asm("mov.b64 %0, {%1, %1};" : "=l"(r) : "r"(u));
    return r;
}
__device__ __forceinline__ ull pack2(float a, float b) {
    ull r; asm("mov.b64 %0, {%1, %2};" : "=l"(r) : "r"(__float_as_uint(a)), "r"(__float_as_uint(b)));
    return r;
}
__device__ __forceinline__ float lo2(ull v) { return __uint_as_float((unsigned)(v & 0xffffffffull)); }
__device__ __forceinline__ float hi2(ull v) { return __uint_as_float((unsigned)(v >> 32)); }
__device__ __forceinline__ int refl(int v, int n) {
    return v < 0 ? -v : (v >= n ? 2 * n - 2 - v : v);
}
// jax bilinear 24->48 weights (edge-renormalized triangle)
__device__ __forceinline__ void upw(int o, int& i0, float& w0, int& i1, float& w1v) {
    if (o & 1) { i0 = (o - 1) >> 1; i1 = i0 + 1; w0 = 0.75f; w1v = 0.25f;
                 if (i1 >= HD) { i1 = i0; w0 = 1.0f; w1v = 0.0f; } }
    else       { i1 = o >> 1; i0 = i1 - 1; w1v = 0.75f; w0 = 0.25f;
                 if (i0 < 0) { i0 = i1; w0 = 0.0f; w1v = 1.0f; } }
}

// ---------------- k_t: NCHW -> pixel-major transpose + GN partial sums + init ----------------
__global__ void __launch_bounds__(256) k_t(const float* __restrict__ x) {
    __shared__ float tile[32][33];
    __shared__ float sS[8][4], sQ[8][4];
    int tx = threadIdx.x & 31, ty = threadIdx.x >> 5;
    int tb = blockIdx.x, cb = blockIdx.y, b = blockIdx.z;
    if (tb == 0 && cb == 0 && b == 0 && threadIdx.x < BB) {
        g_dmin[threadIdx.x] = 0x7f7fffff; g_dmax[threadIdx.x] = 0;
    }
    int c0 = cb * 32, p0 = tb * 32;
    #pragma unroll
    for (int k = 0; k < 4; k++) {
        int c = c0 + ty + 8 * k;
        float v = x[(b * CC + c) * PP + p0 + tx];
        tile[ty + 8 * k][tx] = v;
        float s = v, q = v * v;
        #pragma unroll
        for (int off = 16; off; off >>= 1) {
            s += __shfl_xor_sync(~0u, s, off);
            q += __shfl_xor_sync(~0u, q, off);
        }
        if (tx == 0) { sS[ty][k] = s; sQ[ty][k] = q; }
    }
    __syncthreads();
    #pragma unroll
    for (int k = 0; k < 4; k++) {
        int p = p0 + ty + 8 * k;
        g_xt[(b * PP + p) * CC + c0 + tx] = tile[tx][ty + 8 * k];
    }
    if (threadIdx.x < 8) {
        int k = threadIdx.x >> 1, m = threadIdx.x & 1;
        float s = sS[4*m][k] + sS[4*m+1][k] + sS[4*m+2][k] + sS[4*m+3][k];
        float q = sQ[4*m][k] + sQ[4*m+1][k] + sQ[4*m+2][k] + sQ[4*m+3][k];
        int g = 8 * cb + threadIdx.x;
        g_gps[(b * NG + g) * NT + tb] = s;
        g_gpq[(b * NG + g) * NT + tb] = q;
    }
}

// ---------------- k_down: 2x2 mean in pixel-major + GN finalize ----------------
__global__ void __launch_bounds__(256) k_down() {
    int idx = blockIdx.x * 256 + threadIdx.x;     // 147456 exact
    int c = idx & 127;
    int rest = idx >> 7;
    int b = rest / DD, od = rest - b * DD;
    int oh = od / HD, ow = od - oh * HD;
    int p00 = (2 * oh) * WW + 2 * ow;
    const float* xb = g_xt + b * PP * CC;
    g_dt[idx] = 0.25f * (xb[p00 * CC + c] + xb[(p00 + 1) * CC + c] +
                         xb[(p00 + WW) * CC + c] + xb[(p00 + WW + 1) * CC + c]);
    if (blockIdx.x < BB * NG) {
        __shared__ float fs[NT], fq[NT];
        int bg = blockIdx.x;
        if (threadIdx.x < NT) {
            fs[threadIdx.x] = g_gps[bg * NT + threadIdx.x];
            fq[threadIdx.x] = g_gpq[bg * NT + threadIdx.x];
        }
        __syncthreads();
        if (threadIdx.x == 0) {
            float s = 0.f, q = 0.f;
            for (int i = 0; i < NT; i++) { s += fs[i]; q += fq[i]; }
            const float invn = 1.0f / (4.0f * PP);
            float mu = s * invn;
            float var = q * invn - mu * mu;
            g_mu[bg] = mu;
            g_rstd[bg] = rsqrtf(var + 1e-5f);
        }
    }
}

// ---------------- k_pix: warp per pixel; df, norm, normalized vector ----------------
__global__ void __launch_bounds__(256) k_pix() {
    int warp = threadIdx.x >> 5, lane = threadIdx.x & 31;
    int pix = blockIdx.x * 8 + warp;              // 576 blocks * 8 = 4608
    int b = pix / PP, p = pix - b * PP;
    int h = p / WW, w = p - h * WW;
    const float4 v4 = *(const float4*)(g_xt + pix * CC + 4 * lane);

    int r0, r1, c0, c1; float wr0, wr1, wc0, wc1;
    upw(h, r0, wr0, r1, wr1);
    upw(w, c0, wc0, c1, wc1);
    const float* db = g_dt + b * DD * CC + 4 * lane;
    const float4 d00 = *(const float4*)(db + (r0 * HD + c0) * CC);
    const float4 d01 = *(const float4*)(db + (r0 * HD + c1) * CC);
    const float4 d10 = *(const float4*)(db + (r1 * HD + c0) * CC);
    const float4 d11 = *(const float4*)(db + (r1 * HD + c1) * CC);

    float a, q = 0.f;
    float x0 = wr0 * (wc0 * d00.x + wc1 * d01.x) + wr1 * (wc0 * d10.x + wc1 * d11.x);
    float x1 = wr0 * (wc0 * d00.y + wc1 * d01.y) + wr1 * (wc0 * d10.y + wc1 * d11.y);
    float x2 = wr0 * (wc0 * d00.z + wc1 * d01.z) + wr1 * (wc0 * d10.z + wc1 * d11.z);
    float x3 = wr0 * (wc0 * d00.w + wc1 * d01.w) + wr1 * (wc0 * d10.w + wc1 * d11.w);
    a = fabsf(v4.x - x0) + fabsf(v4.y - x1) + fabsf(v4.z - x2) + fabsf(v4.w - x3);
    q = v4.x * v4.x + v4.y * v4.y + v4.z * v4.z + v4.w * v4.w;
    #pragma unroll
    for (int off = 16; off; off >>= 1) {
        a += __shfl_xor_sync(~0u, a, off);
        q += __shfl_xor_sync(~0u, q, off);
    }
    float m = fmaxf(sqrtf(q), 1e-12f);            // all lanes hold full sums
    if (lane == 0) {
        g_df[pix] = a;
        atomicMin(&g_dmin[b], __float_as_int(a));
        atomicMax(&g_dmax[b], __float_as_int(a));
        g_m[pix] = m;
    }
    float inv = 1.0f / m;
    float4 o; o.x = v4.x * inv; o.y = v4.y * inv; o.z = v4.z * inv; o.w = v4.w * inv;
    *(float4*)(g_xn + pix * CC + 4 * lane) = o;
}

// ---------------- k_main: sims + stable top-k + gather + GN fuse ----------------
__global__ void __launch_bounds__(256) k_main(const float* __restrict__ gamma,
                                              const float* __restrict__ beta) {
    int warp = threadIdx.x >> 5, lane = threadIdx.x & 31;
    int pix = blockIdx.x * 8 + warp;
    int b = pix / PP, p = pix - b * PP;
    int h = p / WW, w = p - h * WW;
    const float* xnb = g_xn + b * PP * CC;
    const float4 xp4 = *(const float4*)(xnb + p * CC + 4 * lane);

    float df = g_df[pix];
    float dmin = __int_as_float(g_dmin[b]);
    float dmax = __int_as_float(g_dmax[b]);
    float dn = (df - dmin) / (dmax - dmin + 1e-8f);
    int kcnt = (int)(1.0f + rintf(dn * 15.0f));
    if (kcnt < 1) kcnt = 1;
    if (kcnt > 16) kcnt = 16;

    int rbase[WIN], qo[WIN];
    #pragma unroll
    for (int t = 0; t < WIN; t++) {
        rbase[t] = refl(h + t - 6, HH) * WW * CC;
        qo[t]    = refl(w + t - 6, WW) * CC;
    }

    float sreg[6];
    #pragma unroll
    for (int r = 0; r < 6; r++) {
        float v[32];
        #pragma unroll
        for (int jj = 0; jj < 32; jj++) {
            const int kk = r * 32 + jj;
            const int ii = (kk < KK2) ? kk / WIN : 0;
            const int ij = (kk < KK2) ? kk - ii * WIN : 0;
            const float4 vq = *(const float4*)(xnb + rbase[ii] + qo[ij] + 4 * lane);
            v[jj] = xp4.x * vq.x + xp4.y * vq.y + xp4.z * vq.z + xp4.w * vq.w;
        }
        #pragma unroll
        for (int off = 16; off >= 1; off >>= 1) {
            bool up = (lane & off) != 0;
            #pragma unroll
            for (int j = 0; j < off; j++) {
                float send = up ? v[j] : v[j + off];
                float recv = __shfl_xor_sync(~0u, send, off);
                v[j] = (up ? v[j + off] : v[j]) + recv;
            }
        }
        sreg[r] = v[0];
    }
    if (160 + lane >= KK2) sreg[5] = -1e30f;

    unsigned taken = 0;
    int selk[16]; float selw[16];
    float sumexp = 0.f;
    #pragma unroll
    for (int it = 0; it < 16; it++) {
        if (it < kcnt) {
            float bv = -1e30f; int bt = 0;
            #pragma unroll
            for (int t = 0; t < 6; t++) {
                float cand = (taken & (1u << t)) ? -1e30f : sreg[t];
                if (cand > bv) { bv = cand; bt = t; }
            }
            int bk = lane + 32 * bt;
            #pragma unroll
            for (int off = 16; off; off >>= 1) {
                float ov = __shfl_xor_sync(~0u, bv, off);
                int   ok = __shfl_xor_sync(~0u, bk, off);
                if (ov > bv || (ov == bv && ok < bk)) { bv = ov; bk = ok; }
            }
            if (lane == (bk & 31)) taken |= (1u << (bk >> 5));
            float e = __expf(bv);
            selk[it] = bk; selw[it] = e; sumexp += e;
        }
    }

    float inv = 1.0f / sumexp;
    float4 out4 = make_float4(0.f, 0.f, 0.f, 0.f);
    #pragma unroll
    for (int it = 0; it < 16; it++) {
        if (it < kcnt) {
            int kk = selk[it];
            int ii = kk / WIN, jj = kk - ii * WIN;
            int r = refl(h + ii - 6, HH);
            int cq = refl(w + jj - 6, WW);
            int q = r * WW + cq;
            float wgt = selw[it] * inv * g_m[b * PP + q];
            const float4 vq = *(const float4*)(xnb + q * CC + 4 * lane);
            out4.x += wgt * vq.x; out4.y += wgt * vq.y;
            out4.z += wgt * vq.z; out4.w += wgt * vq.w;
        }
    }

    float mp = g_m[pix];
    float mu = g_mu[b * NG + lane];
    float rs = g_rstd[b * NG + lane];
    float4 gm  = *(const float4*)(gamma + 4 * lane);
    float4 bt4 = *(const float4*)(beta + 4 * lane);
    float4 e4;
    e4.x = out4.x + (xp4.x * mp - mu) * rs * gm.x + bt4.x;
    e4.y = out4.y + (xp4.y * mp - mu) * rs * gm.y + bt4.y;
    e4.z = out4.z + (xp4.z * mp - mu) * rs * gm.z + bt4.z;
    e4.w = out4.w + (xp4.w * mp - mu) * rs * gm.w + bt4.w;
    *(float4*)(g_enh + pix * CC + 4 * lane) = e4;
}

// ---------------- k_ffn: register-tiled GEMM pair, f32x2, 48KB smem ----------------
// Block = 256 threads, 32 pixels. sE k-major [128][32] (16KB), sH k-major [256][32] (32KB).
__global__ void __launch_bounds__(256) k_ffn(const float* __restrict__ w1,
                                             const float* __restrict__ b1,
                                             const float* __restrict__ w2,
                                             const float* __restrict__ b2,
                                             float* __restrict__ out) {
    __shared__ __align__(16) ull sE_u[128 * 16];   // [k][p2] px-paired, 16KB
    __shared__ __align__(16) ull sH_u[256 * 16];   // [n][p2] px-paired, 32KB
    float* sE_f = (float*)sE_u;
    int tid = threadIdx.x;
    int pix0 = blockIdx.x * 32;
    int b = pix0 / PP;

    // fill sE transposed: float idx = k*32 + p
    {
        const float4* eg = (const float4*)(g_enh + pix0 * CC);
        #pragma unroll
        for (int i = 0; i < 4; i++) {
            int idx = tid + 256 * i;               // 1024 float4 = 32px * 32c4
            int p = idx >> 5, c4 = idx & 31;
            float4 v = eg[idx];
            sE_f[(4 * c4 + 0) * 32 + p] = v.x;
            sE_f[(4 * c4 + 1) * 32 + p] = v.y;
            sE_f[(4 * c4 + 2) * 32 + p] = v.z;
            sE_f[(4 * c4 + 3) * 32 + p] = v.w;
        }
    }
    __syncthreads();

    int pi = tid & 3;          // px tile: 8 px (4 ull pairs)
    int ni = tid >> 2;         // 0..63

    // ---- GEMM1: H[n][p] = relu(W1 E + b1); thread: n = ni*4..+3, px = pi*8..+7 ----
    {
        ull acc[4][4];
        #pragma unroll
        for (int m = 0; m < 4; m++)
            #pragma unroll
            for (int j = 0; j < 4; j++) acc[m][j] = 0ull;
        const float4* w1v4 = (const float4*)w1;
        #pragma unroll 2
        for (int kt = 0; kt < 32; kt++) {
            float4 wv[4];
            #pragma unroll
            for (int m = 0; m < 4; m++) wv[m] = w1v4[(ni * 4 + m) * 32 + kt];
            ulonglong2 e2[4][2];
            #pragma unroll
            for (int kk = 0; kk < 4; kk++) {
                const ulonglong2* ep = (const ulonglong2*)(sE_u + (4 * kt + kk) * 16 + pi * 4);
                e2[kk][0] = ep[0]; e2[kk][1] = ep[1];
            }
            #pragma unroll
            for (int kk = 0; kk < 4; kk++) {
                #pragma unroll
                for (int m = 0; m < 4; m++) {
                    float wf = (kk == 0) ? wv[m].x : (kk == 1) ? wv[m].y : (kk == 2) ? wv[m].z : wv[m].w;
                    ull wd = dup2(wf);
                    fma2(acc[m][0], e2[kk][0].x, wd, acc[m][0]);
                    fma2(acc[m][1], e2[kk][0].y, wd, acc[m][1]);
                    fma2(acc[m][2], e2[kk][1].x, wd, acc[m][2]);
                    fma2(acc[m][3], e2[kk][1].y, wd, acc[m][3]);
                }
            }
        }
        #pragma unroll
        for (int m = 0; m < 4; m++) {
            int n = ni * 4 + m;
            float bb = b1[n];
            #pragma unroll
            for (int j = 0; j < 4; j++) {
                float l = fmaxf(lo2(acc[m][j]) + bb, 0.f);
                float hgh = fmaxf(hi2(acc[m][j]) + bb, 0.f);
                sH_u[n * 16 + pi * 4 + j] = pack2(l, hgh);
            }
        }
    }
    __syncthreads();

    // ---- GEMM2 + residual: out = E + W2 H + b2; thread: c = ci*2..+1, px = pi*8..+7 ----
    {
        int ci = ni;           // 0..63 -> 2 channels each
        ull acc[2][4];
        #pragma unroll
        for (int m = 0; m < 2; m++)
            #pragma unroll
            for (int j = 0; j < 4; j++) acc[m][j] = 0ull;
        const float4* w2v4 = (const float4*)w2;
        #pragma unroll 2
        for (int nt = 0; nt < 64; nt++) {
            float4 wv[2];
            wv[0] = w2v4[(ci * 2 + 0) * 64 + nt];
            wv[1] = w2v4[(ci * 2 + 1) * 64 + nt];
            ulonglong2 h2[4][2];
            #pragma unroll
            for (int kk = 0; kk < 4; kk++) {
                const ulonglong2* hp = (const ulonglong2*)(sH_u + (4 * nt + kk) * 16 + pi * 4);
                h2[kk][0] = hp[0]; h2[kk][1] = hp[1];
            }
            #pragma unroll
            for (int kk = 0; kk < 4; kk++) {
                #pragma unroll
                for (int m = 0; m < 2; m++) {
                    float wf = (kk == 0) ? wv[m].x : (kk == 1) ? wv[m].y : (kk == 2) ? wv[m].z : wv[m].w;
                    ull wd = dup2(wf);
                    fma2(acc[m][0], h2[kk][0].x, wd, acc[m][0]);
                    fma2(acc[m][1], h2[kk][0].y, wd, acc[m][1]);
                    fma2(acc[m][2], h2[kk][1].x, wd, acc[m][2]);
                    fma2(acc[m][3], h2[kk][1].y, wd, acc[m][3]);
                }
            }
        }
        #pragma unroll
        for (int m = 0; m < 2; m++) {
            int c = ci * 2 + m;
            ull bbd = dup2(b2[c]);
            float* og = out + (b * CC + c) * PP + (pix0 - b * PP) + pi * 8;
            #pragma unroll
            for (int j = 0; j < 4; j++) {
                ull ev = sE_u[c * 16 + pi * 4 + j];
                ull r;
                add2(r, acc[m][j], ev);
                add2(r, r, bbd);
                *(ull*)(og + 2 * j) = r;
            }
        }
    }
}

extern "C" void kernel_launch(void* const* d_in, const int* in_sizes, int n_in,
                              void* d_out, int out_size) {
    const float* x     = (const float*)d_in[0];
    const float* gamma = (const float*)d_in[1];
    const float* beta  = (const float*)d_in[2];
    const float* w1    = (const float*)d_in[3];
    const float* b1    = (const float*)d_in[4];
    const float* w2    = (const float*)d_in[5];
    const float* b2    = (const float*)d_in[6];
    float* out = (float*)d_out;

    dim3 gT(NT, 4, BB);
    k_t<<<gT, 256>>>(x);
    k_down<<<(BB * DD * CC) / 256, 256>>>();
    k_pix<<<BB * PP / 8, 256>>>();
    k_main<<<(BB * PP) / 8, 256>>>(gamma, beta);
    k_ffn<<<(BB * PP) / 32, 256>>>(w1, b1, w2, b2, out);
}